// round 6
// baseline (speedup 1.0000x reference)
#include <cuda_runtime.h>
#include <stdint.h>
#include <math.h>

#define DN 256
#define NN 128
#define SD 132            // scratch row stride (floats)
#define NTHREADS 512
#define NWARPS (NTHREADS / 32)
#define SMEM_BYTES (129 * SD * 4)

// Master matrix: G eliminated through current front t (device-global scratch).
__device__ float g_A[DN * DN];
// Shadow diagonal chain: (G[q,q]-1) followed by the same update chain.
__device__ float g_dv1[DN];
// Precomputed gumbel noise per (step k, position i) — data independent.
__device__ float g_gum[NN * DN];

// ---------------------------------------------------------------------------
// Threefry-2x32, 20 rounds (JAX-compatible)
// ---------------------------------------------------------------------------
__device__ __forceinline__ void threefry(uint32_t k0, uint32_t k1,
                                         uint32_t x0, uint32_t x1,
                                         uint32_t &o0, uint32_t &o1)
{
    uint32_t ks2 = k0 ^ k1 ^ 0x1BD11BDAu;
#define TFR(r) { x0 += x1; x1 = (x1 << r) | (x1 >> (32 - r)); x1 ^= x0; }
    x0 += k0; x1 += k1;
    TFR(13) TFR(15) TFR(26) TFR(6)
    x0 += k1;  x1 += ks2 + 1u;
    TFR(17) TFR(29) TFR(16) TFR(24)
    x0 += ks2; x1 += k0 + 2u;
    TFR(13) TFR(15) TFR(26) TFR(6)
    x0 += k0;  x1 += k1 + 3u;
    TFR(17) TFR(29) TFR(16) TFR(24)
    x0 += k1;  x1 += ks2 + 4u;
    TFR(13) TFR(15) TFR(26) TFR(6)
    x0 += ks2; x1 += k0 + 5u;
#undef TFR
    o0 = x0; o1 = x1;
}

// ---------------------------------------------------------------------------
// G = I - P P^T  (exact fp32, serial ascending-k fma accumulation)
// ---------------------------------------------------------------------------
__global__ void g_init_kernel(const float* __restrict__ P)
{
    __shared__ float Ta[16][129];
    __shared__ float Tb[16][129];
    const int bi = blockIdx.y * 16;
    const int bj = blockIdx.x * 16;
    for (int e = threadIdx.x; e < 16 * 128; e += 256) {
        int r = e >> 7, c = e & 127;
        Ta[r][c] = P[(bi + r) * 128 + c];
        Tb[r][c] = P[(bj + r) * 128 + c];
    }
    __syncthreads();
    const int ty = threadIdx.x >> 4, tx = threadIdx.x & 15;
    float acc = 0.0f;
#pragma unroll 8
    for (int m = 0; m < 128; m++)
        acc = __fmaf_rn(Ta[ty][m], Tb[tx][m], acc);
    const int gi = bi + ty, gj = bj + tx;
    g_A[gi * DN + gj] = __fsub_rn((gi == gj) ? 1.0f : 0.0f, acc);
}

// ---------------------------------------------------------------------------
// Precompute gumbel noise — JAX partitionable threefry bits path (bit-exact)
// ---------------------------------------------------------------------------
__global__ void gumbel_init_kernel()
{
    const int k = blockIdx.x;      // step
    const int i = threadIdx.x;     // position 0..255
    uint32_t kk0, kk1;
    threefry(0u, 42u, 0u, (uint32_t)k, kk0, kk1);     // fold_in(key(42), k)
    uint32_t o0, o1;
    threefry(kk0, kk1, 0u, (uint32_t)i, o0, o1);      // counter64 = i
    const uint32_t bits = o0 ^ o1;                     // 64->32 fold
    const float f = __uint_as_float((bits >> 9) | 0x3f800000u) - 1.0f;
    const float TINYF = 1.17549435e-38f;
    const float uu = fmaxf(TINYF, __fadd_rn(f, TINYF));
    const float nl = (float)(-log((double)uu));
    const float g  = -(float)(log((double)nl));
    g_gum[k * DN + i] = g;
}

__device__ __forceinline__ float piv_safe_rcp(float pv)
{
    const float pvs = (fabsf(pv) > 1e-30f) ? pv : 1e-30f;
    return __frcp_rn(pvs);
}

// ---------------------------------------------------------------------------
// Persistent single-CTA sampler: 128 sequential steps (incremental front).
// Per-column single reciprocal, producer-pipelined; fma updates; fp32 logs.
// ---------------------------------------------------------------------------
__global__ __launch_bounds__(NTHREADS, 1)
void sampler_kernel(float* __restrict__ out, int out_size)
{
    extern __shared__ float S[];          // scratch block, SD-stride rows
    __shared__ float piv[DN];
    __shared__ float probs[DN];
    __shared__ float occ[DN];
    __shared__ float um[DN];
    __shared__ float tr[512];             // associative-scan down-sweep levels
    __shared__ float ts[512];             // associative-scan up-sweep levels
    __shared__ float wr[NWARPS];
    __shared__ int   wi[NWARPS];
    __shared__ float sh_rinv[2];
    __shared__ int   sh_t, sh_pos;
    __shared__ float sh_ps;

    const int tid = threadIdx.x;
    const int wid = tid >> 5, lid = tid & 31;
    const float NEGINF = __int_as_float(0xff800000);
    const int offs[9] = {0, 256, 384, 448, 480, 496, 504, 508, 510};

    for (int i = tid; i < DN; i += NTHREADS) {
        occ[i] = 0.0f;
        g_dv1[i] = __fsub_rn(g_A[i * DN + i], 1.0f);
    }
    if (tid == 0) { sh_t = 0; sh_ps = 1.0f; }
    __syncthreads();

    for (int k = 0; k < NN; k++) {
        const int t = sh_t;
        const int xmax = DN - NN + k + 1;   // 129 + k
        const int s = xmax - t;             // <= 129

        // ---- copy active master block [t:xmax)^2 into shared scratch ----
        for (int r = wid; r < s; r += NWARPS) {
            const float* src = g_A + (t + r) * DN + t;
            float* dst = S + r * SD;
            for (int c = lid; c < s; c += 32) dst[c] = src[c];
        }
        __syncthreads();

        // ---- prologue: pivot 0 + its reciprocal ----
        if (tid == 0) {
            const float pv = S[0];
            piv[t] = pv;
            sh_rinv[0] = piv_safe_rcp(pv);
        }
        __syncthreads();

        // ---- speculative elimination, one sync per column ----
        // li = A[i,j] * rcp(piv_safe);  A[i,c] = fma(-li, A[j,c], A[i,c])
        // (rcp*mul + fma are ulp-level deviations, evidenced trajectory-safe)
        for (int j = 0; j < s; j++) {
            const float rinv = sh_rinv[j & 1];
            const int jp = j + 1;
            const int cc = jp + lid;
            const float* uro = S + j * SD;
            const float u0 = (cc      < s) ? uro[cc     ] : 0.0f;
            const float u1 = (cc + 32 < s) ? uro[cc + 32] : 0.0f;
            const float u2 = (cc + 64 < s) ? uro[cc + 64] : 0.0f;
            const float u3 = (cc + 96 < s) ? uro[cc + 96] : 0.0f;
            for (int i = jp + wid; i < s; i += NWARPS) {
                const float li = __fmul_rn(S[i * SD + j], rinv);
                float* row = S + i * SD;
                if (cc < s) {
                    const float v = __fmaf_rn(-li, u0, row[cc]);
                    row[cc] = v;
                    // producer: element (jp, jp) -> next pivot + reciprocal
                    if (wid == 0 && lid == 0 && i == jp) {
                        piv[t + jp] = v;
                        sh_rinv[jp & 1] = piv_safe_rcp(v);
                    }
                }
                if (cc + 32 < s) row[cc + 32] = __fmaf_rn(-li, u1, row[cc + 32]);
                if (cc + 64 < s) row[cc + 64] = __fmaf_rn(-li, u2, row[cc + 64]);
                if (cc + 96 < s) row[cc + 96] = __fmaf_rn(-li, u3, row[cc + 96]);
            }
            __syncthreads();
        }

        // ---- u_m (masked pivots) ----
        for (int i = tid; i < DN; i += NTHREADS)
            um[i] = (i >= t && i < xmax) ? piv[i] : 1.0f;
        __syncthreads();

        // ---- cumprod via associative-scan tree (bit-exact pairing) ----
        for (int i = tid; i < DN; i += NTHREADS) tr[i] = um[i];
        __syncthreads();
        for (int L = 1; L <= 8; L++) {
            const int n = DN >> L;
            for (int i = tid; i < n; i += NTHREADS)
                tr[offs[L] + i] = __fmul_rn(tr[offs[L-1] + 2*i], tr[offs[L-1] + 2*i + 1]);
            __syncthreads();
        }
        if (tid == 0) ts[offs[8]] = tr[offs[8]];
        __syncthreads();
        for (int L = 7; L >= 0; L--) {
            const int n = DN >> L;
            for (int i = tid; i < n; i += NTHREADS) {
                float v;
                if (i == 0)       v = tr[offs[L]];
                else if (i & 1)   v = ts[offs[L+1] + ((i - 1) >> 1)];
                else              v = __fmul_rn(ts[offs[L+1] + (i >> 1) - 1], tr[offs[L] + i]);
                ts[offs[L] + i] = v;
            }
            __syncthreads();
        }

        // ---- probs on support ----
        for (int j = tid; j < DN; j += NTHREADS) {
            if (j >= t && j < xmax) {
                const float c = (j == 0) ? 1.0f : ts[j - 1];
                const float p = __fmul_rn(__fsub_rn(1.0f, um[j]), c);
                probs[j] = (fabsf(p) > 1e-15f) ? p : 0.0f;
            } else {
                probs[j] = 0.0f;
            }
        }
        __syncthreads();

        // ---- gumbel-categorical argmax (fp32 log; gumbel bit-exact fp64) ----
        float v = NEGINF;
        int bi = 1 << 30;
        if (tid < DN) {
            const float p = probs[tid];
            const float logit = (p > 0.0f) ? logf(p) : NEGINF;
            v = __fadd_rn(g_gum[k * DN + tid], logit);
            bi = tid;
        }
        for (int off = 16; off; off >>= 1) {
            const float ov = __shfl_down_sync(0xffffffffu, v, off);
            const int   oi = __shfl_down_sync(0xffffffffu, bi, off);
            if (ov > v || (ov == v && oi < bi)) { v = ov; bi = oi; }
        }
        if (lid == 0) { wr[wid] = v; wi[wid] = bi; }
        __syncthreads();
        if (tid == 0) {
            float bv = wr[0]; int bx = wi[0];
            for (int w = 1; w < NWARPS; w++)
                if (wr[w] > bv || (wr[w] == bv && wi[w] < bx)) { bv = wr[w]; bx = wi[w]; }
            sh_pos = bx;
            occ[bx] = 1.0f;
            sh_ps = __fmul_rn(sh_ps, probs[bx]);
        }
        __syncthreads();

        // ---- commit rows t..pos into master (advance front to pos+1) ----
        const int pos = sh_pos;
        if (k < NN - 1) {
            for (int j = t; j <= pos; j++) {
                if (tid == 0) {
                    if (j == pos)
                        g_A[pos * DN + pos] = g_dv1[pos];   // -1-from-step-0 chain
                    sh_rinv[0] = piv_safe_rcp(g_A[j * DN + j]);
                }
                __syncthreads();
                const float rinv = sh_rinv[0];
                const int cc = j + 1 + lid;
                const float* uro = g_A + j * DN;
                float uu[8];
#pragma unroll
                for (int m = 0; m < 8; m++) {
                    const int c = cc + 32 * m;
                    uu[m] = (c < DN) ? uro[c] : 0.0f;
                }
                for (int i = j + 1 + wid; i < DN; i += NWARPS) {
                    const float li = __fmul_rn(g_A[i * DN + j], rinv);
                    float* row = g_A + i * DN;
#pragma unroll
                    for (int m = 0; m < 8; m++) {
                        const int c = cc + 32 * m;
                        if (c < DN) {
                            row[c] = __fmaf_rn(-li, uu[m], row[c]);
                            if (c == i) g_dv1[i] = __fmaf_rn(-li, uu[m], g_dv1[i]);
                        }
                    }
                }
                __syncthreads();
            }
            if (tid == 0) sh_t = pos + 1;
        }
        __syncthreads();
    }

    // ---- outputs: occ_vec (256) then prob_sample (1) ----
    for (int i = tid; i < DN && i < out_size; i += NTHREADS) out[i] = occ[i];
    if (tid == 0 && out_size > DN) out[DN] = sh_ps;
    for (int i = DN + 1 + tid; i < out_size; i += NTHREADS) out[i] = 0.0f;
}

// ---------------------------------------------------------------------------
extern "C" void kernel_launch(void* const* d_in, const int* in_sizes, int n_in,
                              void* d_out, int out_size)
{
    const float* P = (const float*)d_in[0];
    float* out = (float*)d_out;

    cudaFuncSetAttribute(sampler_kernel,
                         cudaFuncAttributeMaxDynamicSharedMemorySize,
                         SMEM_BYTES);

    g_init_kernel<<<dim3(16, 16), 256>>>(P);
    gumbel_init_kernel<<<NN, DN>>>();
    sampler_kernel<<<1, NTHREADS, SMEM_BYTES>>>(out, out_size);
}

// round 7
// speedup vs baseline: 1.3534x; 1.3534x over previous
#include <cuda_runtime.h>
#include <stdint.h>
#include <math.h>

#define DN 256
#define NN 128
#define SD 132            // scratch row stride (floats)
#define NTHREADS 1024
#define NWARPS 32
#define SMEM_BYTES (129 * SD * 4)

// Master matrix: G eliminated through current front t (device-global scratch).
__device__ float g_A[DN * DN];
// Shadow diagonal chain: (G[q,q]-1) + identical update chain (ref has -1 from step 0).
__device__ float g_dv1[DN];
// Precomputed gumbel noise per (step k, position i) — data independent.
__device__ float g_gum[NN * DN];

// ---------------------------------------------------------------------------
// Threefry-2x32, 20 rounds (JAX-compatible)
// ---------------------------------------------------------------------------
__device__ __forceinline__ void threefry(uint32_t k0, uint32_t k1,
                                         uint32_t x0, uint32_t x1,
                                         uint32_t &o0, uint32_t &o1)
{
    uint32_t ks2 = k0 ^ k1 ^ 0x1BD11BDAu;
#define TFR(r) { x0 += x1; x1 = (x1 << r) | (x1 >> (32 - r)); x1 ^= x0; }
    x0 += k0; x1 += k1;
    TFR(13) TFR(15) TFR(26) TFR(6)
    x0 += k1;  x1 += ks2 + 1u;
    TFR(17) TFR(29) TFR(16) TFR(24)
    x0 += ks2; x1 += k0 + 2u;
    TFR(13) TFR(15) TFR(26) TFR(6)
    x0 += k0;  x1 += k1 + 3u;
    TFR(17) TFR(29) TFR(16) TFR(24)
    x0 += k1;  x1 += ks2 + 4u;
    TFR(13) TFR(15) TFR(26) TFR(6)
    x0 += ks2; x1 += k0 + 5u;
#undef TFR
    o0 = x0; o1 = x1;
}

// ---------------------------------------------------------------------------
// G = I - P P^T  (exact fp32, serial ascending-k fma accumulation)
// ---------------------------------------------------------------------------
__global__ void g_init_kernel(const float* __restrict__ P)
{
    __shared__ float Ta[16][129];
    __shared__ float Tb[16][129];
    const int bi = blockIdx.y * 16;
    const int bj = blockIdx.x * 16;
    for (int e = threadIdx.x; e < 16 * 128; e += 256) {
        int r = e >> 7, c = e & 127;
        Ta[r][c] = P[(bi + r) * 128 + c];
        Tb[r][c] = P[(bj + r) * 128 + c];
    }
    __syncthreads();
    const int ty = threadIdx.x >> 4, tx = threadIdx.x & 15;
    float acc = 0.0f;
#pragma unroll 8
    for (int m = 0; m < 128; m++)
        acc = __fmaf_rn(Ta[ty][m], Tb[tx][m], acc);
    const int gi = bi + ty, gj = bj + tx;
    g_A[gi * DN + gj] = __fsub_rn((gi == gj) ? 1.0f : 0.0f, acc);
}

// ---------------------------------------------------------------------------
// Precompute gumbel noise — JAX partitionable threefry bits path (bit-exact)
// ---------------------------------------------------------------------------
__global__ void gumbel_init_kernel()
{
    const int k = blockIdx.x;      // step
    const int i = threadIdx.x;     // position 0..255
    uint32_t kk0, kk1;
    threefry(0u, 42u, 0u, (uint32_t)k, kk0, kk1);     // fold_in(key(42), k)
    uint32_t o0, o1;
    threefry(kk0, kk1, 0u, (uint32_t)i, o0, o1);      // counter64 = i
    const uint32_t bits = o0 ^ o1;                     // 64->32 fold
    const float f = __uint_as_float((bits >> 9) | 0x3f800000u) - 1.0f;
    const float TINYF = 1.17549435e-38f;
    const float uu = fmaxf(TINYF, __fadd_rn(f, TINYF));
    const float nl = (float)(-log((double)uu));
    const float g  = -(float)(log((double)nl));
    g_gum[k * DN + i] = g;
}

__device__ __forceinline__ float piv_safe_rcp(float pv)
{
    const float pvs = (fabsf(pv) > 1e-30f) ? pv : 1e-30f;
    return __frcp_rn(pvs);
}

__device__ __forceinline__ int ld_acq_shared(const int* p)
{
    int v;
    uint32_t a = (uint32_t)__cvta_generic_to_shared((void*)p);
    asm volatile("ld.acquire.cta.shared.b32 %0, [%1];" : "=r"(v) : "r"(a) : "memory");
    return v;
}

__device__ __forceinline__ void st_rel_shared(int* p, int v)
{
    uint32_t a = (uint32_t)__cvta_generic_to_shared((void*)p);
    asm volatile("st.release.cta.shared.b32 [%0], %1;" :: "r"(a), "r"(v) : "memory");
}

// ---------------------------------------------------------------------------
// Persistent single-CTA sampler: 128 sequential steps (incremental front).
// Speculative LU runs as a warp wavefront: row ownership = row % 32, pivot-row
// handoff via acquire/release smem flags — no per-column CTA barrier.
// ---------------------------------------------------------------------------
__global__ __launch_bounds__(NTHREADS, 1)
void sampler_kernel(float* __restrict__ out, int out_size)
{
    extern __shared__ float S[];          // scratch block, SD-stride rows
    __shared__ float piv[DN];
    __shared__ float occ[DN];
    __shared__ float rinvs[SD];
    __shared__ int   flags[SD];
    __shared__ float sh_rinv;
    __shared__ int   sh_t, sh_pos;
    __shared__ float sh_ps;

    const int tid = threadIdx.x;
    const int wid = tid >> 5, lid = tid & 31;
    const float NEGINF = __int_as_float(0xff800000);

    for (int i = tid; i < DN; i += NTHREADS) {
        occ[i] = 0.0f;
        g_dv1[i] = __fsub_rn(g_A[i * DN + i], 1.0f);
    }
    if (tid == 0) { sh_t = 0; sh_ps = 1.0f; }
    __syncthreads();

    for (int k = 0; k < NN; k++) {
        const int t = sh_t;
        const int xmax = DN - NN + k + 1;   // 129 + k
        const int s = xmax - t;             // <= 129

        // ---- copy active master block [t:xmax)^2 into shared scratch ----
        for (int r = wid; r < s; r += NWARPS) {
            const float* src = g_A + (t + r) * DN + t;
            float* dst = S + r * SD;
            for (int c = lid; c < s; c += 32) dst[c] = src[c];
        }
        for (int i = tid; i < SD; i += NTHREADS) flags[i] = 0;
        __syncthreads();

        // ---- seed pivot 0 (release publishes to spinning consumers) ----
        if (tid == 0) {
            const float pv = S[0];
            piv[t] = pv;
            rinvs[0] = piv_safe_rcp(pv);
            st_rel_shared(&flags[0], 1);
        }

        // ---- wavefront speculative elimination (no CTA barriers) ----
        // li = A[i,j] * rcp(piv_safe);  A[i,c] = fma(-li, A[j,c], A[i,c])
        for (int j = 0; j < s - 1; j++) {
            const int base = j + 1;
            const int rstart = base + ((wid - (base & 31)) & 31);
            if (rstart >= s) break;               // no owned rows remain
            while (ld_acq_shared(&flags[j]) == 0) {}
            const float rinv = rinvs[j];
            const int cc = base + lid;
            const float* uro = S + j * SD;
            const float u0 = (cc      < s) ? uro[cc     ] : 0.0f;
            const float u1 = (cc + 32 < s) ? uro[cc + 32] : 0.0f;
            const float u2 = (cc + 64 < s) ? uro[cc + 64] : 0.0f;
            const float u3 = (cc + 96 < s) ? uro[cc + 96] : 0.0f;
            for (int i = rstart; i < s; i += 32) {
                const float li = __fmul_rn(S[i * SD + j], rinv);
                float* row = S + i * SD;
                float vdiag = 0.0f;
                if (cc < s) { vdiag = __fmaf_rn(-li, u0, row[cc]); row[cc] = vdiag; }
                if (cc + 32 < s) row[cc + 32] = __fmaf_rn(-li, u1, row[cc + 32]);
                if (cc + 64 < s) row[cc + 64] = __fmaf_rn(-li, u2, row[cc + 64]);
                if (cc + 96 < s) row[cc + 96] = __fmaf_rn(-li, u3, row[cc + 96]);
                if (i == base) {                  // publish pivot row j+1
                    if (lid == 0) { piv[t + i] = vdiag; rinvs[i] = piv_safe_rcp(vdiag); }
                    __syncwarp();
                    if (lid == 0) st_rel_shared(&flags[i], 1);
                }
            }
        }
        __syncthreads();

        // ---- single-warp sampling: scan + probs + gumbel argmax ----
        if (wid == 0) {
            const int ch = (s + 31) >> 5;         // <= 5 slots per lane
            const int lo = lid * ch;
            float u[5], gum[5];
            float lp = 1.0f;
#pragma unroll
            for (int m = 0; m < 5; m++) {
                const int idx = lo + m;
                const bool ok = (m < ch) && (idx < s);
                u[m]   = ok ? piv[t + idx] : 1.0f;
                gum[m] = ok ? g_gum[k * DN + (t + idx)] : 0.0f;
                lp = __fmul_rn(lp, u[m]);
            }
            // inclusive warp scan of lane products, then shift to exclusive
            float run = lp;
            for (int d = 1; d < 32; d <<= 1) {
                const float v = __shfl_up_sync(0xffffffffu, run, d);
                if (lid >= d) run = __fmul_rn(v, run);
            }
            float c = __shfl_up_sync(0xffffffffu, run, 1);
            if (lid == 0) c = 1.0f;

            float best = NEGINF, bprob = 0.0f;
            int bidx = 1 << 30;
#pragma unroll
            for (int m = 0; m < 5; m++) {
                const int idx = lo + m;
                if (m < ch && idx < s) {
                    float p = __fmul_rn(__fsub_rn(1.0f, u[m]), c);
                    p = (fabsf(p) > 1e-15f) ? p : 0.0f;
                    c = __fmul_rn(c, u[m]);
                    if (p > 0.0f) {
                        const float vv = __fadd_rn(gum[m], logf(p));
                        if (vv > best) { best = vv; bidx = idx; bprob = p; }
                    }
                }
            }
            for (int off = 16; off; off >>= 1) {
                const float ov = __shfl_down_sync(0xffffffffu, best, off);
                const int   oi = __shfl_down_sync(0xffffffffu, bidx, off);
                const float op = __shfl_down_sync(0xffffffffu, bprob, off);
                if (ov > best || (ov == best && oi < bidx)) { best = ov; bidx = oi; bprob = op; }
            }
            if (lid == 0) {
                const int pos = (bidx == (1 << 30)) ? 0 : (t + bidx);  // all -inf -> argmax=0
                const float psel = (bidx == (1 << 30)) ? 0.0f : bprob;
                sh_pos = pos;
                occ[pos] = 1.0f;
                sh_ps = __fmul_rn(sh_ps, psel);
            }
        }
        __syncthreads();

        // ---- commit rows t..pos into master (advance front to pos+1) ----
        const int pos = sh_pos;
        if (k < NN - 1) {
            for (int j = t; j <= pos; j++) {
                if (tid == 0) {
                    if (j == pos)
                        g_A[pos * DN + pos] = g_dv1[pos];   // -1-from-step-0 chain
                    sh_rinv = piv_safe_rcp(g_A[j * DN + j]);
                }
                __syncthreads();
                const float rinv = sh_rinv;
                const int cc = j + 1 + lid;
                const float* uro = g_A + j * DN;
                float uu[8];
#pragma unroll
                for (int m = 0; m < 8; m++) {
                    const int c = cc + 32 * m;
                    uu[m] = (c < DN) ? uro[c] : 0.0f;
                }
                for (int i = j + 1 + wid; i < DN; i += NWARPS) {
                    const float li = __fmul_rn(g_A[i * DN + j], rinv);
                    float* row = g_A + i * DN;
#pragma unroll
                    for (int m = 0; m < 8; m++) {
                        const int c = cc + 32 * m;
                        if (c < DN) {
                            row[c] = __fmaf_rn(-li, uu[m], row[c]);
                            if (c == i) g_dv1[i] = __fmaf_rn(-li, uu[m], g_dv1[i]);
                        }
                    }
                }
                __syncthreads();
            }
            if (tid == 0) sh_t = pos + 1;
        }
        __syncthreads();
    }

    // ---- outputs: occ_vec (256) then prob_sample (1) ----
    for (int i = tid; i < DN && i < out_size; i += NTHREADS) out[i] = occ[i];
    if (tid == 0 && out_size > DN) out[DN] = sh_ps;
    for (int i = DN + 1 + tid; i < out_size; i += NTHREADS) out[i] = 0.0f;
}

// ---------------------------------------------------------------------------
extern "C" void kernel_launch(void* const* d_in, const int* in_sizes, int n_in,
                              void* d_out, int out_size)
{
    const float* P = (const float*)d_in[0];
    float* out = (float*)d_out;

    cudaFuncSetAttribute(sampler_kernel,
                         cudaFuncAttributeMaxDynamicSharedMemorySize,
                         SMEM_BYTES);

    g_init_kernel<<<dim3(16, 16), 256>>>(P);
    gumbel_init_kernel<<<NN, DN>>>();
    sampler_kernel<<<1, NTHREADS, SMEM_BYTES>>>(out, out_size);
}